// round 9
// baseline (speedup 1.0000x reference)
#include <cuda_runtime.h>
#include <cstdint>
#include <math.h>

// Problem constants (fixed by the reference)
#define BATCH   2
#define SEQ     2048
#define EMB     512
#define HEADS   8
#define DHEAD   64
#define WINHALF 128         // WIN/2

#define M1 (BATCH*SEQ)      // 4096 rows
#define N1 (3*EMB)          // 1536 (qkv)
#define KDIM EMB            // 512

// Scratch: __device__ globals (no allocation allowed anywhere)
__device__ float g_qkv[(size_t)M1 * N1];     // [B,S, H*(q|k|v)*64]  ~25 MB
__device__ float g_ctx[(size_t)M1 * EMB];    // attention output [B,S,E] ~8 MB

// ===========================================================================
// Helpers: mma.sync tf32 (SM80-compatible path, valid on compute_100)
// ===========================================================================
__device__ __forceinline__ uint32_t f2tf32(float x) {
    uint32_t r;
    asm("cvt.rna.tf32.f32 %0, %1;" : "=r"(r) : "f"(x));
    return r;
}

__device__ __forceinline__ void mma_tf32_16x8x8(
    float* c, uint32_t a0, uint32_t a1, uint32_t a2, uint32_t a3,
    uint32_t b0, uint32_t b1)
{
    asm volatile(
        "mma.sync.aligned.m16n8k8.row.col.f32.tf32.tf32.f32 "
        "{%0,%1,%2,%3}, {%4,%5,%6,%7}, {%8,%9}, {%0,%1,%2,%3};"
        : "+f"(c[0]), "+f"(c[1]), "+f"(c[2]), "+f"(c[3])
        : "r"(a0), "r"(a1), "r"(a2), "r"(a3), "r"(b0), "r"(b1));
}

__device__ __forceinline__ uint32_t smem_u32(const void* p) {
    return (uint32_t)__cvta_generic_to_shared(p);
}

#define CP_ASYNC16(dst_u32, src_ptr) \
    asm volatile("cp.async.cg.shared.global [%0], [%1], 16;" \
                 :: "r"(dst_u32), "l"(src_ptr))
#define CP_COMMIT() asm volatile("cp.async.commit_group;" ::: "memory")
#define CP_WAIT(n)  asm volatile("cp.async.wait_group %0;" :: "n"(n) : "memory")

// ===========================================================================
// tf32 tensor-core GEMM: C[M,N] = A[M,K] @ B[K,N] + bias[N]
// A row-major [M,K], B row-major [K,N] (native layouts, no transpose).
// 128x128 CTA tile, BK=32, 8 warps (2x4), warp tile 64x32,
// m16n8k8 tf32 mma, cp.async double buffering. 256 threads.
// Dynamic smem: As[2][128*36] + Bs[2][32*136] = 71,680 B.
// Requires M%128==0, N%128==0, K%32==0.
// ===========================================================================
#define BM 128
#define BN 128
#define BK 32
#define APAD 36    // As row stride (floats): 32 data + 4 pad (banks distinct)
#define BPAD 136   // Bs row stride (floats): 128 data + 8 pad (banks distinct)

#define GEMM_SMEM_BYTES ((2 * BM * APAD + 2 * BK * BPAD) * (int)sizeof(float))

__global__ __launch_bounds__(256) void mma_gemm_kernel(
    const float* __restrict__ A, const float* __restrict__ B,
    const float* __restrict__ bias, float* __restrict__ C,
    int M, int N, int K)
{
    extern __shared__ float smem[];
    float* AsBase = smem;                    // 2 stages of BM*APAD
    float* BsBase = smem + 2 * BM * APAD;    // 2 stages of BK*BPAD

    const int tid  = threadIdx.x;
    const int lane = tid & 31;
    const int wid  = tid >> 5;
    const int wm   = wid & 1;            // 0..1  (warp row)
    const int wn   = wid >> 1;           // 0..3  (warp col)
    const int m0   = blockIdx.y * BM;
    const int n0   = blockIdx.x * BN;

    // Fragment coordinates (PTX m16n8k8 tf32 thread mappings)
    const int aRow = wm * 64 + (lane >> 2);   // + mi*16 (+8)
    const int aCol = lane & 3;                 // + ks*8 (+4)
    const int bCol = wn * 32 + (lane >> 2);   // + ni*8
    const int bRow = lane & 3;                 // + ks*8 (+4)

    float acc[4][4][4];
    #pragma unroll
    for (int mi = 0; mi < 4; mi++)
        #pragma unroll
        for (int ni = 0; ni < 4; ni++)
            #pragma unroll
            for (int r = 0; r < 4; r++) acc[mi][ni][r] = 0.f;

    const int nch = K / BK;

    // --- async tile loader: stage s, chunk ch ---
    auto load_tiles = [&](int s, int ch) {
        const int k0 = ch * BK;
        float* As_ = AsBase + s * BM * APAD;
        float* Bs_ = BsBase + s * BK * BPAD;
        // A: 128 rows x 32 floats -> 1024 float4, 4 per thread
        #pragma unroll
        for (int i = 0; i < 4; i++) {
            const int idx = tid + i * 256;
            const int row = idx >> 3;
            const int c4  = (idx & 7) << 2;
            const float* src = A + (size_t)(m0 + row) * K + k0 + c4;
            CP_ASYNC16(smem_u32(&As_[row * APAD + c4]), src);
        }
        // B: 32 rows x 128 floats -> 1024 float4, 4 per thread
        #pragma unroll
        for (int i = 0; i < 4; i++) {
            const int idx = tid + i * 256;
            const int row = idx >> 5;
            const int c4  = (idx & 31) << 2;
            const float* src = B + (size_t)(k0 + row) * N + n0 + c4;
            CP_ASYNC16(smem_u32(&Bs_[row * BPAD + c4]), src);
        }
        CP_COMMIT();
    };

    load_tiles(0, 0);

    for (int ch = 0; ch < nch; ch++) {
        const int s = ch & 1;
        if (ch + 1 < nch) {
            load_tiles(s ^ 1, ch + 1);
            CP_WAIT(1);           // tiles for chunk ch are resident
        } else {
            CP_WAIT(0);
        }
        __syncthreads();

        const float* As_ = AsBase + s * BM * APAD;
        const float* Bs_ = BsBase + s * BK * BPAD;

        #pragma unroll
        for (int ks = 0; ks < 4; ks++) {
            const int k0 = ks * 8;
            uint32_t bf[4][2];
            #pragma unroll
            for (int ni = 0; ni < 4; ni++) {
                bf[ni][0] = f2tf32(Bs_[(k0 + bRow)     * BPAD + bCol + ni * 8]);
                bf[ni][1] = f2tf32(Bs_[(k0 + bRow + 4) * BPAD + bCol + ni * 8]);
            }
            #pragma unroll
            for (int mi = 0; mi < 4; mi++) {
                const int r0 = (aRow + mi * 16) * APAD;
                const int r8 = (aRow + mi * 16 + 8) * APAD;
                uint32_t a0 = f2tf32(As_[r0 + k0 + aCol]);
                uint32_t a1 = f2tf32(As_[r8 + k0 + aCol]);
                uint32_t a2 = f2tf32(As_[r0 + k0 + aCol + 4]);
                uint32_t a3 = f2tf32(As_[r8 + k0 + aCol + 4]);
                #pragma unroll
                for (int ni = 0; ni < 4; ni++)
                    mma_tf32_16x8x8(acc[mi][ni], a0, a1, a2, a3,
                                    bf[ni][0], bf[ni][1]);
            }
        }
        __syncthreads();   // compute done before next prefetch overwrites
    }

    // Epilogue: c0:(r,c) c1:(r,c+1) c2:(r+8,c) c3:(r+8,c+1)
    const int crow = m0 + wm * 64 + (lane >> 2);
    const int ccol = n0 + wn * 32 + ((lane & 3) << 1);
    #pragma unroll
    for (int mi = 0; mi < 4; mi++) {
        #pragma unroll
        for (int ni = 0; ni < 4; ni++) {
            const int col = ccol + ni * 8;
            const float bx = bias[col], by = bias[col + 1];
            float2 v0, v1;
            v0.x = acc[mi][ni][0] + bx;  v0.y = acc[mi][ni][1] + by;
            v1.x = acc[mi][ni][2] + bx;  v1.y = acc[mi][ni][3] + by;
            *(float2*)(C + (size_t)(crow + mi * 16)     * N + col) = v0;
            *(float2*)(C + (size_t)(crow + mi * 16 + 8) * N + col) = v1;
        }
    }
}

// ---------------------------------------------------------------------------
// Fused banded attention (flash-style), unchanged.
// ---------------------------------------------------------------------------
__global__ __launch_bounds__(256) void attn_kernel(
    const float* __restrict__ qkv, const int* __restrict__ pmask,
    float* __restrict__ ctx)
{
    extern __shared__ float sm[];
    float (*Qs)[65] = (float(*)[65])sm;                   // 64x65
    float (*Ks)[65] = (float(*)[65])(sm + 64 * 65);       // 64x65 (reused for P)
    float (*Vs)[65] = (float(*)[65])(sm + 2 * 64 * 65);   // 64x65
    __shared__ float m_sh[64], l_sh[64];

    const int tid = threadIdx.x;
    const int tx = tid & 15, ty = tid >> 4;
    const int r0 = blockIdx.x * 64;
    const int b  = blockIdx.y >> 3;
    const int h  = blockIdx.y & 7;

    const float* base = qkv + (size_t)b * SEQ * N1 + h * (3 * DHEAD);

    for (int idx = tid; idx < 64 * 16; idx += 256) {
        const int row = idx >> 4;
        const int c4  = (idx & 15) << 2;
        float4 v = *(const float4*)(base + (size_t)(r0 + row) * N1 + c4);
        Qs[row][c4 + 0] = v.x * 0.125f;
        Qs[row][c4 + 1] = v.y * 0.125f;
        Qs[row][c4 + 2] = v.z * 0.125f;
        Qs[row][c4 + 3] = v.w * 0.125f;
    }
    if (tid < 64) { m_sh[tid] = -1e30f; l_sh[tid] = 0.f; }

    float o[4][4];
    #pragma unroll
    for (int i = 0; i < 4; i++)
        #pragma unroll
        for (int j = 0; j < 4; j++) o[i][j] = 0.f;

    int gri[4];
    #pragma unroll
    for (int i = 0; i < 4; i++) gri[i] = r0 + ty * 4 + i;

    for (int kt = 0; kt < 5; kt++) {
        const int c0 = r0 - WINHALF + kt * 64;
        if (c0 + 63 < 0 || c0 >= SEQ) continue;

        __syncthreads();

        for (int idx = tid; idx < 64 * 16; idx += 256) {
            const int row = idx >> 4;
            const int c4  = (idx & 15) << 2;
            const int gc = c0 + row;
            float4 kv = make_float4(0.f, 0.f, 0.f, 0.f);
            float4 vv = make_float4(0.f, 0.f, 0.f, 0.f);
            if (gc >= 0 && gc < SEQ) {
                kv = *(const float4*)(base + (size_t)gc * N1 + DHEAD + c4);
                vv = *(const float4*)(base + (size_t)gc * N1 + 2 * DHEAD + c4);
            }
            Ks[row][c4 + 0] = kv.x; Ks[row][c4 + 1] = kv.y;
            Ks[row][c4 + 2] = kv.z; Ks[row][c4 + 3] = kv.w;
            Vs[row][c4 + 0] = vv.x; Vs[row][c4 + 1] = vv.y;
            Vs[row][c4 + 2] = vv.z; Vs[row][c4 + 3] = vv.w;
        }
        __syncthreads();

        float s[4][4];
        #pragma unroll
        for (int i = 0; i < 4; i++)
            #pragma unroll
            for (int j = 0; j < 4; j++) s[i][j] = 0.f;

        #pragma unroll 8
        for (int k = 0; k < 64; k++) {
            float ar[4], br[4];
            #pragma unroll
            for (int i = 0; i < 4; i++) ar[i] = Qs[ty * 4 + i][k];
            #pragma unroll
            for (int j = 0; j < 4; j++) br[j] = Ks[tx * 4 + j][k];
            #pragma unroll
            for (int i = 0; i < 4; i++)
                #pragma unroll
                for (int j = 0; j < 4; j++)
                    s[i][j] += ar[i] * br[j];
        }

        int gcj[4]; bool cv[4];
        #pragma unroll
        for (int j = 0; j < 4; j++) {
            gcj[j] = c0 + tx * 4 + j;
            cv[j] = (gcj[j] >= 0) && (gcj[j] < SEQ) &&
                    (pmask[b * SEQ + gcj[j]] == 1);
        }
        #pragma unroll
        for (int i = 0; i < 4; i++)
            #pragma unroll
            for (int j = 0; j < 4; j++) {
                const int d = gcj[j] - gri[i];
                if (!cv[j] || d > WINHALF || d < -WINHALF) s[i][j] = -1e30f;
            }

        float p[4][4];
        #pragma unroll
        for (int i = 0; i < 4; i++) {
            const int row = ty * 4 + i;
            float tm = fmaxf(fmaxf(s[i][0], s[i][1]), fmaxf(s[i][2], s[i][3]));
            #pragma unroll
            for (int off = 8; off >= 1; off >>= 1)
                tm = fmaxf(tm, __shfl_xor_sync(0xffffffffu, tm, off));
            const float mo = m_sh[row];
            const float mn = fmaxf(mo, tm);
            const float sc = __expf(mo - mn);
            float ts = 0.f;
            #pragma unroll
            for (int j = 0; j < 4; j++) {
                p[i][j] = (s[i][j] > -1e29f) ? __expf(s[i][j] - mn) : 0.f;
                ts += p[i][j];
            }
            #pragma unroll
            for (int off = 8; off >= 1; off >>= 1)
                ts += __shfl_xor_sync(0xffffffffu, ts, off);
            if (tx == 0) { m_sh[row] = mn; l_sh[row] = l_sh[row] * sc + ts; }
            #pragma unroll
            for (int j = 0; j < 4; j++) o[i][j] *= sc;
        }

        __syncthreads();
        #pragma unroll
        for (int i = 0; i < 4; i++)
            #pragma unroll
            for (int j = 0; j < 4; j++)
                Ks[ty * 4 + i][tx * 4 + j] = p[i][j];
        __syncthreads();

        #pragma unroll 8
        for (int c = 0; c < 64; c++) {
            float pr[4], vr[4];
            #pragma unroll
            for (int i = 0; i < 4; i++) pr[i] = Ks[ty * 4 + i][c];
            #pragma unroll
            for (int j = 0; j < 4; j++) vr[j] = Vs[c][tx * 4 + j];
            #pragma unroll
            for (int i = 0; i < 4; i++)
                #pragma unroll
                for (int j = 0; j < 4; j++)
                    o[i][j] += pr[i] * vr[j];
        }
    }
    __syncthreads();

    #pragma unroll
    for (int i = 0; i < 4; i++) {
        const int row = r0 + ty * 4 + i;
        const float l = l_sh[ty * 4 + i];
        const float inv = (l > 0.f && pmask[b * SEQ + row] == 1) ? 1.f / l : 0.f;
        float4 v;
        v.x = o[i][0] * inv; v.y = o[i][1] * inv;
        v.z = o[i][2] * inv; v.w = o[i][3] * inv;
        *(float4*)(ctx + (size_t)(b * SEQ + row) * EMB + h * DHEAD + tx * 4) = v;
    }
}

// ---------------------------------------------------------------------------
// Launch
// ---------------------------------------------------------------------------
extern "C" void kernel_launch(void* const* d_in, const int* in_sizes, int n_in,
                              void* d_out, int out_size)
{
    const float* x     = (const float*)d_in[0];
    const int*   pmask = (const int*)  d_in[1];
    const float* Wqkv  = (const float*)d_in[2];
    const float* bqkv  = (const float*)d_in[3];
    const float* Wo    = (const float*)d_in[4];
    const float* bo    = (const float*)d_in[5];
    float* out = (float*)d_out;

    float *qkv, *ctx;
    cudaGetSymbolAddress((void**)&qkv, g_qkv);
    cudaGetSymbolAddress((void**)&ctx, g_ctx);

    cudaFuncSetAttribute(mma_gemm_kernel,
                         cudaFuncAttributeMaxDynamicSharedMemorySize,
                         GEMM_SMEM_BYTES);

    // 1) QKV projection: [4096,512] @ [512,1536] + bqkv  (tf32 mma.sync)
    {
        dim3 grid(N1 / BN, M1 / BM);
        mma_gemm_kernel<<<grid, 256, GEMM_SMEM_BYTES>>>(x, Wqkv, bqkv, qkv,
                                                        M1, N1, KDIM);
    }

    // 2) Banded attention
    {
        const int smem = 3 * 64 * 65 * (int)sizeof(float);  // 49,920 B
        cudaFuncSetAttribute(attn_kernel,
                             cudaFuncAttributeMaxDynamicSharedMemorySize, smem);
        dim3 grid(SEQ / 64, BATCH * HEADS);
        attn_kernel<<<grid, 256, smem>>>(qkv, pmask, ctx);
    }

    // 3) Output projection: [4096,512] @ [512,512] + bo  (tf32 mma.sync)
    {
        dim3 grid(EMB / BN, M1 / BM);
        mma_gemm_kernel<<<grid, 256, GEMM_SMEM_BYTES>>>(ctx, Wo, bo, out,
                                                        M1, EMB, KDIM);
    }
}

// round 10
// speedup vs baseline: 1.5285x; 1.5285x over previous
#include <cuda_runtime.h>
#include <cstdint>
#include <math.h>

// Problem constants (fixed by the reference)
#define BATCH   2
#define SEQ     2048
#define EMB     512
#define HEADS   8
#define DHEAD   64
#define WINHALF 128         // WIN/2

#define M1 (BATCH*SEQ)      // 4096 rows
#define N1 (3*EMB)          // 1536 (qkv)
#define KDIM EMB            // 512

// Scratch: __device__ globals (no allocation allowed anywhere)
__device__ float g_qkv[(size_t)M1 * N1];     // [B,S, H*(q|k|v)*64]  ~25 MB
__device__ float g_ctx[(size_t)M1 * EMB];    // attention output [B,S,E] ~8 MB

// ===========================================================================
// Helpers: mma.sync tf32 (SM80-compatible path, valid on compute_100)
// ===========================================================================
__device__ __forceinline__ uint32_t f2tf32(float x) {
    uint32_t r;
    asm("cvt.rna.tf32.f32 %0, %1;" : "=r"(r) : "f"(x));
    return r;
}
__device__ __forceinline__ float tf32r(float x) {   // round-to-tf32, as float
    uint32_t r = f2tf32(x);
    return __uint_as_float(r);
}

__device__ __forceinline__ void mma_tf32_16x8x8(
    float* c, uint32_t a0, uint32_t a1, uint32_t a2, uint32_t a3,
    uint32_t b0, uint32_t b1)
{
    asm volatile(
        "mma.sync.aligned.m16n8k8.row.col.f32.tf32.tf32.f32 "
        "{%0,%1,%2,%3}, {%4,%5,%6,%7}, {%8,%9}, {%0,%1,%2,%3};"
        : "+f"(c[0]), "+f"(c[1]), "+f"(c[2]), "+f"(c[3])
        : "r"(a0), "r"(a1), "r"(a2), "r"(a3), "r"(b0), "r"(b1));
}

__device__ __forceinline__ uint32_t smem_u32(const void* p) {
    return (uint32_t)__cvta_generic_to_shared(p);
}

#define CP_ASYNC16(dst_u32, src_ptr) \
    asm volatile("cp.async.cg.shared.global [%0], [%1], 16;" \
                 :: "r"(dst_u32), "l"(src_ptr))
#define CP_COMMIT() asm volatile("cp.async.commit_group;" ::: "memory")
#define CP_WAIT(n)  asm volatile("cp.async.wait_group %0;" :: "n"(n) : "memory")

// ===========================================================================
// tf32 tensor-core GEMM: C[M,N] = A[M,K] @ B[K,N] + bias[N]
// 128x128 CTA tile, BK=16, 3-stage cp.async pipeline, 8 warps (2x4),
// warp tile 64x32, m16n8k8 tf32 mma. 256 threads.
// Dynamic smem: 3*(128*20 + 16*136)*4 = 56,832 B  -> 2 CTAs/SM.
// ===========================================================================
#define BM 128
#define BN 128
#define BK 16
#define NST 3
#define APAD 20    // As row stride: 16 data + 4 pad; (20r+c)%32 distinct
#define BPAD 136   // Bs row stride: 128 data + 8 pad; (136k+n)%32 distinct

#define GEMM_SMEM_BYTES ((NST * (BM * APAD + BK * BPAD)) * (int)sizeof(float))

__global__ __launch_bounds__(256) void mma_gemm_kernel(
    const float* __restrict__ A, const float* __restrict__ B,
    const float* __restrict__ bias, float* __restrict__ C,
    int M, int N, int K)
{
    extern __shared__ float smem[];
    float* AsBase = smem;                        // NST stages of BM*APAD
    float* BsBase = smem + NST * BM * APAD;      // NST stages of BK*BPAD

    const int tid  = threadIdx.x;
    const int lane = tid & 31;
    const int wid  = tid >> 5;
    const int wm   = wid & 1;            // 0..1  (warp row)
    const int wn   = wid >> 1;           // 0..3  (warp col)
    const int m0   = blockIdx.y * BM;
    const int n0   = blockIdx.x * BN;

    const int aRow = wm * 64 + (lane >> 2);
    const int aCol = lane & 3;
    const int bCol = wn * 32 + (lane >> 2);
    const int bRow = lane & 3;

    float acc[4][4][4];
    #pragma unroll
    for (int mi = 0; mi < 4; mi++)
        #pragma unroll
        for (int ni = 0; ni < 4; ni++)
            #pragma unroll
            for (int r = 0; r < 4; r++) acc[mi][ni][r] = 0.f;

    const int nch = K / BK;   // 32

    auto load_tiles = [&](int s, int ch) {
        const int k0 = ch * BK;
        float* As_ = AsBase + s * BM * APAD;
        float* Bs_ = BsBase + s * BK * BPAD;
        // A: 128 rows x 16 floats -> 512 float4, 2 per thread
        #pragma unroll
        for (int i = 0; i < 2; i++) {
            const int idx = tid + i * 256;
            const int row = idx >> 2;
            const int c4  = (idx & 3) << 2;
            const float* src = A + (size_t)(m0 + row) * K + k0 + c4;
            CP_ASYNC16(smem_u32(&As_[row * APAD + c4]), src);
        }
        // B: 16 rows x 128 floats -> 512 float4, 2 per thread
        #pragma unroll
        for (int i = 0; i < 2; i++) {
            const int idx = tid + i * 256;
            const int row = idx >> 5;
            const int c4  = (idx & 31) << 2;
            const float* src = B + (size_t)(k0 + row) * N + n0 + c4;
            CP_ASYNC16(smem_u32(&Bs_[row * BPAD + c4]), src);
        }
        CP_COMMIT();
    };

    load_tiles(0, 0);
    load_tiles(1, 1);

    for (int ch = 0; ch < nch; ch++) {
        if (ch < nch - 1) { CP_WAIT(1); } else { CP_WAIT(0); }
        __syncthreads();
        if (ch + 2 < nch) load_tiles((ch + 2) % NST, ch + 2);

        const int s = ch % NST;
        const float* As_ = AsBase + s * BM * APAD;
        const float* Bs_ = BsBase + s * BK * BPAD;

        #pragma unroll
        for (int ks = 0; ks < 2; ks++) {
            const int k0 = ks * 8;
            uint32_t bf[4][2];
            #pragma unroll
            for (int ni = 0; ni < 4; ni++) {
                bf[ni][0] = f2tf32(Bs_[(k0 + bRow)     * BPAD + bCol + ni * 8]);
                bf[ni][1] = f2tf32(Bs_[(k0 + bRow + 4) * BPAD + bCol + ni * 8]);
            }
            #pragma unroll
            for (int mi = 0; mi < 4; mi++) {
                const int r0 = (aRow + mi * 16) * APAD;
                const int r8 = (aRow + mi * 16 + 8) * APAD;
                uint32_t a0 = f2tf32(As_[r0 + k0 + aCol]);
                uint32_t a1 = f2tf32(As_[r8 + k0 + aCol]);
                uint32_t a2 = f2tf32(As_[r0 + k0 + aCol + 4]);
                uint32_t a3 = f2tf32(As_[r8 + k0 + aCol + 4]);
                #pragma unroll
                for (int ni = 0; ni < 4; ni++)
                    mma_tf32_16x8x8(acc[mi][ni], a0, a1, a2, a3,
                                    bf[ni][0], bf[ni][1]);
            }
        }
        // no trailing sync: next iteration's CP_WAIT + __syncthreads orders
        // reuse (stage (ch+3)%NST == ch%NST is only overwritten after the
        // barrier that all threads reach having finished compute(ch)).
    }

    const int crow = m0 + wm * 64 + (lane >> 2);
    const int ccol = n0 + wn * 32 + ((lane & 3) << 1);
    #pragma unroll
    for (int mi = 0; mi < 4; mi++) {
        #pragma unroll
        for (int ni = 0; ni < 4; ni++) {
            const int col = ccol + ni * 8;
            const float bx = bias[col], by = bias[col + 1];
            float2 v0, v1;
            v0.x = acc[mi][ni][0] + bx;  v0.y = acc[mi][ni][1] + by;
            v1.x = acc[mi][ni][2] + bx;  v1.y = acc[mi][ni][3] + by;
            *(float2*)(C + (size_t)(crow + mi * 16)     * N + col) = v0;
            *(float2*)(C + (size_t)(crow + mi * 16 + 8) * N + col) = v1;
        }
    }
}

// ===========================================================================
// Fused banded attention on tensor cores (flash-style, tf32 mma).
// 128 threads = 4 warps; block handles one (b,h) x 64 query rows.
// Warp w owns rows [w*16, w*16+16): full-width fragments -> softmax is
// warp-local (quad shuffles). P round-trips through warp-private smem rows.
// smem strides: Qs/Ks/Ps 68 (4r+c banks), Vs 72 (8c+r banks) - conflict-free.
// ===========================================================================
#define QPAD 68
#define VPAD 72
#define ATT_SMEM_BYTES ((3 * 64 * QPAD + 64 * VPAD) * (int)sizeof(float) + 64 * (int)sizeof(int))

__global__ __launch_bounds__(128) void attn_mma_kernel(
    const float* __restrict__ qkv, const int* __restrict__ pmask,
    float* __restrict__ ctx)
{
    extern __shared__ float sm[];
    float* Qs = sm;                       // [64][68]
    float* Ks = sm + 64 * QPAD;           // [64][68]
    float* Ps = sm + 2 * 64 * QPAD;       // [64][68]
    float* Vs = sm + 3 * 64 * QPAD;       // [64][72]
    int*   pms = (int*)(sm + 3 * 64 * QPAD + 64 * VPAD);  // [64]

    const int tid  = threadIdx.x;
    const int lane = tid & 31;
    const int wid  = tid >> 5;
    const int rq   = lane >> 2;    // 0..7
    const int cq   = lane & 3;     // 0..3
    const int wr0  = wid * 16;

    const int r0 = blockIdx.x * 64;
    const int b  = blockIdx.y >> 3;
    const int h  = blockIdx.y & 7;

    const float* base = qkv + (size_t)b * SEQ * N1 + h * (3 * DHEAD);

    // Load Q tile (pre-scaled by 1/8, tf32-rounded)
    #pragma unroll
    for (int i = 0; i < 8; i++) {
        const int idx = tid + i * 128;
        const int row = idx >> 4;
        const int c4  = (idx & 15) << 2;
        float4 v = *(const float4*)(base + (size_t)(r0 + row) * N1 + c4);
        float* q = Qs + row * QPAD + c4;
        q[0] = tf32r(v.x * 0.125f); q[1] = tf32r(v.y * 0.125f);
        q[2] = tf32r(v.z * 0.125f); q[3] = tf32r(v.w * 0.125f);
    }

    float o[8][4];
    #pragma unroll
    for (int ni = 0; ni < 8; ni++)
        #pragma unroll
        for (int r = 0; r < 4; r++) o[ni][r] = 0.f;
    float m_old0 = -1e30f, m_old1 = -1e30f;
    float l0 = 0.f, l1 = 0.f;

    const int gr0 = r0 + wr0 + rq;
    const int gr1 = gr0 + 8;

    for (int kt = 0; kt < 5; kt++) {
        const int c0 = r0 - WINHALF + kt * 64;
        if (c0 + 63 < 0 || c0 >= SEQ) continue;   // uniform across block

        __syncthreads();   // Q ready (first pass) / prev tile fully consumed

        // Load K,V tile (zero-fill out-of-range), tf32-rounded; pmask tile
        #pragma unroll
        for (int i = 0; i < 8; i++) {
            const int idx = tid + i * 128;
            const int row = idx >> 4;
            const int c4  = (idx & 15) << 2;
            const int gc  = c0 + row;
            float4 kv = make_float4(0.f, 0.f, 0.f, 0.f);
            float4 vv = make_float4(0.f, 0.f, 0.f, 0.f);
            if (gc >= 0 && gc < SEQ) {
                kv = *(const float4*)(base + (size_t)gc * N1 + DHEAD + c4);
                vv = *(const float4*)(base + (size_t)gc * N1 + 2 * DHEAD + c4);
            }
            float* kp = Ks + row * QPAD + c4;
            kp[0] = tf32r(kv.x); kp[1] = tf32r(kv.y);
            kp[2] = tf32r(kv.z); kp[3] = tf32r(kv.w);
            float* vp = Vs + row * VPAD + c4;
            vp[0] = tf32r(vv.x); vp[1] = tf32r(vv.y);
            vp[2] = tf32r(vv.z); vp[3] = tf32r(vv.w);
        }
        if (tid < 64) {
            const int gc = c0 + tid;
            pms[tid] = (gc >= 0 && gc < SEQ) ? pmask[b * SEQ + gc] : 0;
        }
        __syncthreads();

        // ---- S = Q @ K^T (warp rows wr0..wr0+15, all 64 cols) ----
        float s[8][4];
        #pragma unroll
        for (int ni = 0; ni < 8; ni++)
            #pragma unroll
            for (int r = 0; r < 4; r++) s[ni][r] = 0.f;

        #pragma unroll
        for (int ks = 0; ks < 8; ks++) {
            const int k0 = ks * 8;
            uint32_t a0 = __float_as_uint(Qs[(wr0 + rq)     * QPAD + k0 + cq]);
            uint32_t a1 = __float_as_uint(Qs[(wr0 + rq + 8) * QPAD + k0 + cq]);
            uint32_t a2 = __float_as_uint(Qs[(wr0 + rq)     * QPAD + k0 + cq + 4]);
            uint32_t a3 = __float_as_uint(Qs[(wr0 + rq + 8) * QPAD + k0 + cq + 4]);
            #pragma unroll
            for (int ni = 0; ni < 8; ni++) {
                uint32_t b0 = __float_as_uint(Ks[(ni * 8 + rq) * QPAD + k0 + cq]);
                uint32_t b1 = __float_as_uint(Ks[(ni * 8 + rq) * QPAD + k0 + cq + 4]);
                mma_tf32_16x8x8(s[ni], a0, a1, a2, a3, b0, b1);
            }
        }

        // ---- band + padding mask ----
        #pragma unroll
        for (int ni = 0; ni < 8; ni++) {
            #pragma unroll
            for (int d = 0; d < 2; d++) {
                const int lc = ni * 8 + 2 * cq + d;
                const int gc = c0 + lc;
                const bool cvalid = (pms[lc] == 1);
                const int d0 = gc - gr0, d1 = gc - gr1;
                if (!cvalid || d0 > WINHALF || d0 < -WINHALF) s[ni][d]     = -1e30f;
                if (!cvalid || d1 > WINHALF || d1 < -WINHALF) s[ni][d + 2] = -1e30f;
            }
        }

        // ---- online softmax (quad-local: rows owned by 4 lanes) ----
        float tm0 = -1e30f, tm1 = -1e30f;
        #pragma unroll
        for (int ni = 0; ni < 8; ni++) {
            tm0 = fmaxf(tm0, fmaxf(s[ni][0], s[ni][1]));
            tm1 = fmaxf(tm1, fmaxf(s[ni][2], s[ni][3]));
        }
        tm0 = fmaxf(tm0, __shfl_xor_sync(0xffffffffu, tm0, 1));
        tm0 = fmaxf(tm0, __shfl_xor_sync(0xffffffffu, tm0, 2));
        tm1 = fmaxf(tm1, __shfl_xor_sync(0xffffffffu, tm1, 1));
        tm1 = fmaxf(tm1, __shfl_xor_sync(0xffffffffu, tm1, 2));

        const float mn0 = fmaxf(m_old0, tm0);
        const float mn1 = fmaxf(m_old1, tm1);
        const float sc0 = __expf(m_old0 - mn0);
        const float sc1 = __expf(m_old1 - mn1);
        m_old0 = mn0; m_old1 = mn1;

        float ts0 = 0.f, ts1 = 0.f;
        float p[8][4];
        #pragma unroll
        for (int ni = 0; ni < 8; ni++) {
            p[ni][0] = (s[ni][0] > -1e29f) ? __expf(s[ni][0] - mn0) : 0.f;
            p[ni][1] = (s[ni][1] > -1e29f) ? __expf(s[ni][1] - mn0) : 0.f;
            p[ni][2] = (s[ni][2] > -1e29f) ? __expf(s[ni][2] - mn1) : 0.f;
            p[ni][3] = (s[ni][3] > -1e29f) ? __expf(s[ni][3] - mn1) : 0.f;
            ts0 += p[ni][0] + p[ni][1];
            ts1 += p[ni][2] + p[ni][3];
        }
        ts0 += __shfl_xor_sync(0xffffffffu, ts0, 1);
        ts0 += __shfl_xor_sync(0xffffffffu, ts0, 2);
        ts1 += __shfl_xor_sync(0xffffffffu, ts1, 1);
        ts1 += __shfl_xor_sync(0xffffffffu, ts1, 2);
        l0 = l0 * sc0 + ts0;
        l1 = l1 * sc1 + ts1;

        #pragma unroll
        for (int ni = 0; ni < 8; ni++) {
            o[ni][0] *= sc0; o[ni][1] *= sc0;
            o[ni][2] *= sc1; o[ni][3] *= sc1;
        }

        // ---- P to warp-private smem rows (tf32-rounded) ----
        #pragma unroll
        for (int ni = 0; ni < 8; ni++) {
            const int col = ni * 8 + 2 * cq;
            Ps[(wr0 + rq)     * QPAD + col]     = tf32r(p[ni][0]);
            Ps[(wr0 + rq)     * QPAD + col + 1] = tf32r(p[ni][1]);
            Ps[(wr0 + rq + 8) * QPAD + col]     = tf32r(p[ni][2]);
            Ps[(wr0 + rq + 8) * QPAD + col + 1] = tf32r(p[ni][3]);
        }
        __syncwarp();

        // ---- O += P @ V ----
        #pragma unroll
        for (int ks = 0; ks < 8; ks++) {
            const int k0 = ks * 8;
            uint32_t a0 = __float_as_uint(Ps[(wr0 + rq)     * QPAD + k0 + cq]);
            uint32_t a1 = __float_as_uint(Ps[(wr0 + rq + 8) * QPAD + k0 + cq]);
            uint32_t a2 = __float_as_uint(Ps[(wr0 + rq)     * QPAD + k0 + cq + 4]);
            uint32_t a3 = __float_as_uint(Ps[(wr0 + rq + 8) * QPAD + k0 + cq + 4]);
            #pragma unroll
            for (int ni = 0; ni < 8; ni++) {
                uint32_t b0 = __float_as_uint(Vs[(k0 + cq)     * VPAD + ni * 8 + rq]);
                uint32_t b1 = __float_as_uint(Vs[(k0 + cq + 4) * VPAD + ni * 8 + rq]);
                mma_tf32_16x8x8(o[ni], a0, a1, a2, a3, b0, b1);
            }
        }
        __syncwarp();
    }

    // ---- normalize + write ctx [B,S,E] ----
    const int pm0 = pmask[b * SEQ + gr0];
    const int pm1 = pmask[b * SEQ + gr1];
    const float inv0 = (l0 > 0.f && pm0 == 1) ? 1.f / l0 : 0.f;
    const float inv1 = (l1 > 0.f && pm1 == 1) ? 1.f / l1 : 0.f;
    float* c0p = ctx + (size_t)(b * SEQ + gr0) * EMB + h * DHEAD;
    float* c1p = ctx + (size_t)(b * SEQ + gr1) * EMB + h * DHEAD;
    #pragma unroll
    for (int ni = 0; ni < 8; ni++) {
        const int col = ni * 8 + 2 * cq;
        float2 v0; v0.x = o[ni][0] * inv0; v0.y = o[ni][1] * inv0;
        float2 v1; v1.x = o[ni][2] * inv1; v1.y = o[ni][3] * inv1;
        *(float2*)(c0p + col) = v0;
        *(float2*)(c1p + col) = v1;
    }
}

// ---------------------------------------------------------------------------
// Launch
// ---------------------------------------------------------------------------
extern "C" void kernel_launch(void* const* d_in, const int* in_sizes, int n_in,
                              void* d_out, int out_size)
{
    const float* x     = (const float*)d_in[0];
    const int*   pmask = (const int*)  d_in[1];
    const float* Wqkv  = (const float*)d_in[2];
    const float* bqkv  = (const float*)d_in[3];
    const float* Wo    = (const float*)d_in[4];
    const float* bo    = (const float*)d_in[5];
    float* out = (float*)d_out;

    float *qkv, *ctx;
    cudaGetSymbolAddress((void**)&qkv, g_qkv);
    cudaGetSymbolAddress((void**)&ctx, g_ctx);

    cudaFuncSetAttribute(mma_gemm_kernel,
                         cudaFuncAttributeMaxDynamicSharedMemorySize,
                         GEMM_SMEM_BYTES);
    cudaFuncSetAttribute(attn_mma_kernel,
                         cudaFuncAttributeMaxDynamicSharedMemorySize,
                         ATT_SMEM_BYTES);

    // 1) QKV projection: [4096,512] @ [512,1536] + bqkv  (tf32 mma.sync)
    {
        dim3 grid(N1 / BN, M1 / BM);
        mma_gemm_kernel<<<grid, 256, GEMM_SMEM_BYTES>>>(x, Wqkv, bqkv, qkv,
                                                        M1, N1, KDIM);
    }

    // 2) Banded attention (tensor-core flash)
    {
        dim3 grid(SEQ / 64, BATCH * HEADS);
        attn_mma_kernel<<<grid, 128, ATT_SMEM_BYTES>>>(qkv, pmask, ctx);
    }

    // 3) Output projection: [4096,512] @ [512,512] + bo  (tf32 mma.sync)
    {
        dim3 grid(EMB / BN, M1 / BM);
        mma_gemm_kernel<<<grid, 256, GEMM_SMEM_BYTES>>>(ctx, Wo, bo, out,
                                                        M1, EMB, KDIM);
    }
}

// round 11
// speedup vs baseline: 1.7413x; 1.1392x over previous
#include <cuda_runtime.h>
#include <cstdint>
#include <math.h>

// Problem constants (fixed by the reference)
#define BATCH   2
#define SEQ     2048
#define EMB     512
#define HEADS   8
#define DHEAD   64
#define WINHALF 128         // WIN/2

#define M1 (BATCH*SEQ)      // 4096 rows
#define N1 (3*EMB)          // 1536 (qkv)
#define KDIM EMB            // 512

// Scratch: __device__ globals (no allocation allowed anywhere)
__device__ float g_qkv[(size_t)M1 * N1];      // tf32-rounded qkv   ~25 MB
__device__ float g_ctx[(size_t)M1 * EMB];     // tf32-rounded ctx    ~8 MB
__device__ float g_xr[(size_t)M1 * KDIM];     // tf32-rounded x      ~8 MB
__device__ float g_wqkvr[(size_t)KDIM * N1];  // tf32-rounded Wqkv   ~3 MB
__device__ float g_wor[(size_t)KDIM * EMB];   // tf32-rounded Wo     ~1 MB

// ===========================================================================
// Helpers: mma.sync tf32 (SM80-compatible path, valid on compute_100)
// ===========================================================================
__device__ __forceinline__ uint32_t f2tf32(float x) {
    uint32_t r;
    asm("cvt.rna.tf32.f32 %0, %1;" : "=r"(r) : "f"(x));
    return r;
}
__device__ __forceinline__ float tf32r(float x) {   // round-to-tf32, as float
    return __uint_as_float(f2tf32(x));
}

__device__ __forceinline__ void mma_tf32_16x8x8(
    float* c, uint32_t a0, uint32_t a1, uint32_t a2, uint32_t a3,
    uint32_t b0, uint32_t b1)
{
    asm volatile(
        "mma.sync.aligned.m16n8k8.row.col.f32.tf32.tf32.f32 "
        "{%0,%1,%2,%3}, {%4,%5,%6,%7}, {%8,%9}, {%0,%1,%2,%3};"
        : "+f"(c[0]), "+f"(c[1]), "+f"(c[2]), "+f"(c[3])
        : "r"(a0), "r"(a1), "r"(a2), "r"(a3), "r"(b0), "r"(b1));
}

__device__ __forceinline__ uint32_t smem_u32(const void* p) {
    return (uint32_t)__cvta_generic_to_shared(p);
}

#define CP_ASYNC16(dst_u32, src_ptr) \
    asm volatile("cp.async.cg.shared.global [%0], [%1], 16;" \
                 :: "r"(dst_u32), "l"(src_ptr))
#define CP_COMMIT() asm volatile("cp.async.commit_group;" ::: "memory")
#define CP_WAIT(n)  asm volatile("cp.async.wait_group %0;" :: "n"(n) : "memory")

// ===========================================================================
// Elementwise tf32 rounding pre-pass (hoists cvts out of GEMM hot loops)
// ===========================================================================
__global__ void round_tf32_kernel(const float* __restrict__ in,
                                  float* __restrict__ out, int n4)
{
    const int i = blockIdx.x * blockDim.x + threadIdx.x;
    if (i < n4) {
        float4 v = ((const float4*)in)[i];
        v.x = tf32r(v.x); v.y = tf32r(v.y);
        v.z = tf32r(v.z); v.w = tf32r(v.w);
        ((float4*)out)[i] = v;
    }
}

// ===========================================================================
// tf32 tensor-core GEMM: C[M,N] = A[M,K] @ B[K,N] + bias[N]
// Inputs pre-rounded to tf32 -> no cvt in the mainloop.
// 128x128 CTA tile, BK=32, 2-stage cp.async, 4 warps (2x2), warp tile 64x64,
// m16n8k8 tf32 mma. 128 threads. smem 71,680 B -> 2 CTAs/SM.
// round_out=1: store tf32-rounded (intermediates consumed by later tf32 math)
// ===========================================================================
#define BM 128
#define BN 128
#define BK 32
#define APAD 36    // As row stride (floats)
#define BPAD 136   // Bs row stride (floats)

#define GEMM_SMEM_BYTES ((2 * BM * APAD + 2 * BK * BPAD) * (int)sizeof(float))

__global__ __launch_bounds__(128, 2) void mma_gemm_kernel(
    const float* __restrict__ A, const float* __restrict__ B,
    const float* __restrict__ bias, float* __restrict__ C,
    int M, int N, int K, int round_out)
{
    extern __shared__ float smem[];
    float* AsBase = smem;                    // 2 stages of BM*APAD
    float* BsBase = smem + 2 * BM * APAD;    // 2 stages of BK*BPAD

    const int tid  = threadIdx.x;
    const int lane = tid & 31;
    const int wid  = tid >> 5;
    const int wm   = wid & 1;            // warp row (2)
    const int wn   = wid >> 1;           // warp col (2)
    const int m0   = blockIdx.y * BM;
    const int n0   = blockIdx.x * BN;

    const int aRow = wm * 64 + (lane >> 2);
    const int aCol = lane & 3;
    const int bColB = wn * 64 + (lane >> 2);
    const int bRow = lane & 3;

    float acc[4][8][4];
    #pragma unroll
    for (int mi = 0; mi < 4; mi++)
        #pragma unroll
        for (int ni = 0; ni < 8; ni++)
            #pragma unroll
            for (int r = 0; r < 4; r++) acc[mi][ni][r] = 0.f;

    const int nch = K / BK;   // 16

    auto load_tiles = [&](int s, int ch) {
        const int k0 = ch * BK;
        float* As_ = AsBase + s * BM * APAD;
        float* Bs_ = BsBase + s * BK * BPAD;
        // A: 128 rows x 32 floats -> 1024 float4, 8 per thread
        #pragma unroll
        for (int i = 0; i < 8; i++) {
            const int idx = tid + i * 128;
            const int row = idx >> 3;
            const int c4  = (idx & 7) << 2;
            const float* src = A + (size_t)(m0 + row) * K + k0 + c4;
            CP_ASYNC16(smem_u32(&As_[row * APAD + c4]), src);
        }
        // B: 32 rows x 128 floats -> 1024 float4, 8 per thread
        #pragma unroll
        for (int i = 0; i < 8; i++) {
            const int idx = tid + i * 128;
            const int row = idx >> 5;
            const int c4  = (idx & 31) << 2;
            const float* src = B + (size_t)(k0 + row) * N + n0 + c4;
            CP_ASYNC16(smem_u32(&Bs_[row * BPAD + c4]), src);
        }
        CP_COMMIT();
    };

    load_tiles(0, 0);

    for (int ch = 0; ch < nch; ch++) {
        const int s = ch & 1;
        if (ch + 1 < nch) {
            load_tiles(s ^ 1, ch + 1);
            CP_WAIT(1);
        } else {
            CP_WAIT(0);
        }
        __syncthreads();

        const float* As_ = AsBase + s * BM * APAD;
        const float* Bs_ = BsBase + s * BK * BPAD;

        #pragma unroll
        for (int ks = 0; ks < 4; ks++) {
            const int k0 = ks * 8;
            uint32_t bf[8][2];
            #pragma unroll
            for (int ni = 0; ni < 8; ni++) {
                bf[ni][0] = __float_as_uint(Bs_[(k0 + bRow)     * BPAD + bColB + ni * 8]);
                bf[ni][1] = __float_as_uint(Bs_[(k0 + bRow + 4) * BPAD + bColB + ni * 8]);
            }
            #pragma unroll
            for (int mi = 0; mi < 4; mi++) {
                const int r0 = (aRow + mi * 16) * APAD;
                const int r8 = (aRow + mi * 16 + 8) * APAD;
                uint32_t a0 = __float_as_uint(As_[r0 + k0 + aCol]);
                uint32_t a1 = __float_as_uint(As_[r8 + k0 + aCol]);
                uint32_t a2 = __float_as_uint(As_[r0 + k0 + aCol + 4]);
                uint32_t a3 = __float_as_uint(As_[r8 + k0 + aCol + 4]);
                #pragma unroll
                for (int ni = 0; ni < 8; ni++)
                    mma_tf32_16x8x8(acc[mi][ni], a0, a1, a2, a3,
                                    bf[ni][0], bf[ni][1]);
            }
        }
        __syncthreads();
    }

    // Epilogue
    const int crow = m0 + wm * 64 + (lane >> 2);
    const int ccol = n0 + wn * 64 + ((lane & 3) << 1);
    #pragma unroll
    for (int mi = 0; mi < 4; mi++) {
        #pragma unroll
        for (int ni = 0; ni < 8; ni++) {
            const int col = ccol + ni * 8;
            const float bx = bias[col], by = bias[col + 1];
            float2 v0, v1;
            v0.x = acc[mi][ni][0] + bx;  v0.y = acc[mi][ni][1] + by;
            v1.x = acc[mi][ni][2] + bx;  v1.y = acc[mi][ni][3] + by;
            if (round_out) {
                v0.x = tf32r(v0.x); v0.y = tf32r(v0.y);
                v1.x = tf32r(v1.x); v1.y = tf32r(v1.y);
            }
            *(float2*)(C + (size_t)(crow + mi * 16)     * N + col) = v0;
            *(float2*)(C + (size_t)(crow + mi * 16 + 8) * N + col) = v1;
        }
    }
}

// ===========================================================================
// Fused banded attention on tensor cores (flash-style, tf32 mma).
// qkv is pre-rounded tf32 (GEMM1 epilogue) -> staging needs no cvt.
// ctx written tf32-rounded for GEMM2.
// ===========================================================================
#define QPAD 68
#define VPAD 72
#define ATT_SMEM_BYTES ((3 * 64 * QPAD + 64 * VPAD) * (int)sizeof(float) + 64 * (int)sizeof(int))

__global__ __launch_bounds__(128) void attn_mma_kernel(
    const float* __restrict__ qkv, const int* __restrict__ pmask,
    float* __restrict__ ctx)
{
    extern __shared__ float sm[];
    float* Qs = sm;                       // [64][68]
    float* Ks = sm + 64 * QPAD;           // [64][68]
    float* Ps = sm + 2 * 64 * QPAD;       // [64][68]
    float* Vs = sm + 3 * 64 * QPAD;       // [64][72]
    int*   pms = (int*)(sm + 3 * 64 * QPAD + 64 * VPAD);  // [64]

    const int tid  = threadIdx.x;
    const int lane = tid & 31;
    const int wid  = tid >> 5;
    const int rq   = lane >> 2;    // 0..7
    const int cq   = lane & 3;     // 0..3
    const int wr0  = wid * 16;

    const int r0 = blockIdx.x * 64;
    const int b  = blockIdx.y >> 3;
    const int h  = blockIdx.y & 7;

    const float* base = qkv + (size_t)b * SEQ * N1 + h * (3 * DHEAD);

    // Load Q tile (scale 1/8 is exact on tf32 values -> no re-round)
    #pragma unroll
    for (int i = 0; i < 8; i++) {
        const int idx = tid + i * 128;
        const int row = idx >> 4;
        const int c4  = (idx & 15) << 2;
        float4 v = *(const float4*)(base + (size_t)(r0 + row) * N1 + c4);
        float* q = Qs + row * QPAD + c4;
        q[0] = v.x * 0.125f; q[1] = v.y * 0.125f;
        q[2] = v.z * 0.125f; q[3] = v.w * 0.125f;
    }

    float o[8][4];
    #pragma unroll
    for (int ni = 0; ni < 8; ni++)
        #pragma unroll
        for (int r = 0; r < 4; r++) o[ni][r] = 0.f;
    float m_old0 = -1e30f, m_old1 = -1e30f;
    float l0 = 0.f, l1 = 0.f;

    const int gr0 = r0 + wr0 + rq;
    const int gr1 = gr0 + 8;

    for (int kt = 0; kt < 5; kt++) {
        const int c0 = r0 - WINHALF + kt * 64;
        if (c0 + 63 < 0 || c0 >= SEQ) continue;   // uniform across block

        __syncthreads();   // Q ready (first pass) / prev tile fully consumed

        // Load K,V tile (zero-fill out-of-range); pmask tile
        #pragma unroll
        for (int i = 0; i < 8; i++) {
            const int idx = tid + i * 128;
            const int row = idx >> 4;
            const int c4  = (idx & 15) << 2;
            const int gc  = c0 + row;
            float4 kv = make_float4(0.f, 0.f, 0.f, 0.f);
            float4 vv = make_float4(0.f, 0.f, 0.f, 0.f);
            if (gc >= 0 && gc < SEQ) {
                kv = *(const float4*)(base + (size_t)gc * N1 + DHEAD + c4);
                vv = *(const float4*)(base + (size_t)gc * N1 + 2 * DHEAD + c4);
            }
            float* kp = Ks + row * QPAD + c4;
            kp[0] = kv.x; kp[1] = kv.y; kp[2] = kv.z; kp[3] = kv.w;
            float* vp = Vs + row * VPAD + c4;
            vp[0] = vv.x; vp[1] = vv.y; vp[2] = vv.z; vp[3] = vv.w;
        }
        if (tid < 64) {
            const int gc = c0 + tid;
            pms[tid] = (gc >= 0 && gc < SEQ) ? pmask[b * SEQ + gc] : 0;
        }
        __syncthreads();

        // ---- S = Q @ K^T ----
        float s[8][4];
        #pragma unroll
        for (int ni = 0; ni < 8; ni++)
            #pragma unroll
            for (int r = 0; r < 4; r++) s[ni][r] = 0.f;

        #pragma unroll
        for (int ks = 0; ks < 8; ks++) {
            const int k0 = ks * 8;
            uint32_t a0 = __float_as_uint(Qs[(wr0 + rq)     * QPAD + k0 + cq]);
            uint32_t a1 = __float_as_uint(Qs[(wr0 + rq + 8) * QPAD + k0 + cq]);
            uint32_t a2 = __float_as_uint(Qs[(wr0 + rq)     * QPAD + k0 + cq + 4]);
            uint32_t a3 = __float_as_uint(Qs[(wr0 + rq + 8) * QPAD + k0 + cq + 4]);
            #pragma unroll
            for (int ni = 0; ni < 8; ni++) {
                uint32_t b0 = __float_as_uint(Ks[(ni * 8 + rq) * QPAD + k0 + cq]);
                uint32_t b1 = __float_as_uint(Ks[(ni * 8 + rq) * QPAD + k0 + cq + 4]);
                mma_tf32_16x8x8(s[ni], a0, a1, a2, a3, b0, b1);
            }
        }

        // ---- band + padding mask ----
        #pragma unroll
        for (int ni = 0; ni < 8; ni++) {
            #pragma unroll
            for (int d = 0; d < 2; d++) {
                const int lc = ni * 8 + 2 * cq + d;
                const int gc = c0 + lc;
                const bool cvalid = (pms[lc] == 1);
                const int d0 = gc - gr0, d1 = gc - gr1;
                if (!cvalid || d0 > WINHALF || d0 < -WINHALF) s[ni][d]     = -1e30f;
                if (!cvalid || d1 > WINHALF || d1 < -WINHALF) s[ni][d + 2] = -1e30f;
            }
        }

        // ---- online softmax (quad-local) ----
        float tm0 = -1e30f, tm1 = -1e30f;
        #pragma unroll
        for (int ni = 0; ni < 8; ni++) {
            tm0 = fmaxf(tm0, fmaxf(s[ni][0], s[ni][1]));
            tm1 = fmaxf(tm1, fmaxf(s[ni][2], s[ni][3]));
        }
        tm0 = fmaxf(tm0, __shfl_xor_sync(0xffffffffu, tm0, 1));
        tm0 = fmaxf(tm0, __shfl_xor_sync(0xffffffffu, tm0, 2));
        tm1 = fmaxf(tm1, __shfl_xor_sync(0xffffffffu, tm1, 1));
        tm1 = fmaxf(tm1, __shfl_xor_sync(0xffffffffu, tm1, 2));

        const float mn0 = fmaxf(m_old0, tm0);
        const float mn1 = fmaxf(m_old1, tm1);
        const float sc0 = __expf(m_old0 - mn0);
        const float sc1 = __expf(m_old1 - mn1);
        m_old0 = mn0; m_old1 = mn1;

        float ts0 = 0.f, ts1 = 0.f;
        float p[8][4];
        #pragma unroll
        for (int ni = 0; ni < 8; ni++) {
            p[ni][0] = (s[ni][0] > -1e29f) ? __expf(s[ni][0] - mn0) : 0.f;
            p[ni][1] = (s[ni][1] > -1e29f) ? __expf(s[ni][1] - mn0) : 0.f;
            p[ni][2] = (s[ni][2] > -1e29f) ? __expf(s[ni][2] - mn1) : 0.f;
            p[ni][3] = (s[ni][3] > -1e29f) ? __expf(s[ni][3] - mn1) : 0.f;
            ts0 += p[ni][0] + p[ni][1];
            ts1 += p[ni][2] + p[ni][3];
        }
        ts0 += __shfl_xor_sync(0xffffffffu, ts0, 1);
        ts0 += __shfl_xor_sync(0xffffffffu, ts0, 2);
        ts1 += __shfl_xor_sync(0xffffffffu, ts1, 1);
        ts1 += __shfl_xor_sync(0xffffffffu, ts1, 2);
        l0 = l0 * sc0 + ts0;
        l1 = l1 * sc1 + ts1;

        #pragma unroll
        for (int ni = 0; ni < 8; ni++) {
            o[ni][0] *= sc0; o[ni][1] *= sc0;
            o[ni][2] *= sc1; o[ni][3] *= sc1;
        }

        // ---- P to warp-private smem rows (tf32-rounded) ----
        #pragma unroll
        for (int ni = 0; ni < 8; ni++) {
            const int col = ni * 8 + 2 * cq;
            Ps[(wr0 + rq)     * QPAD + col]     = tf32r(p[ni][0]);
            Ps[(wr0 + rq)     * QPAD + col + 1] = tf32r(p[ni][1]);
            Ps[(wr0 + rq + 8) * QPAD + col]     = tf32r(p[ni][2]);
            Ps[(wr0 + rq + 8) * QPAD + col + 1] = tf32r(p[ni][3]);
        }
        __syncwarp();

        // ---- O += P @ V ----
        #pragma unroll
        for (int ks = 0; ks < 8; ks++) {
            const int k0 = ks * 8;
            uint32_t a0 = __float_as_uint(Ps[(wr0 + rq)     * QPAD + k0 + cq]);
            uint32_t a1 = __float_as_uint(Ps[(wr0 + rq + 8) * QPAD + k0 + cq]);
            uint32_t a2 = __float_as_uint(Ps[(wr0 + rq)     * QPAD + k0 + cq + 4]);
            uint32_t a3 = __float_as_uint(Ps[(wr0 + rq + 8) * QPAD + k0 + cq + 4]);
            #pragma unroll
            for (int ni = 0; ni < 8; ni++) {
                uint32_t b0 = __float_as_uint(Vs[(k0 + cq)     * VPAD + ni * 8 + rq]);
                uint32_t b1 = __float_as_uint(Vs[(k0 + cq + 4) * VPAD + ni * 8 + rq]);
                mma_tf32_16x8x8(o[ni], a0, a1, a2, a3, b0, b1);
            }
        }
        __syncwarp();
    }

    // ---- normalize + write ctx [B,S,E] (tf32-rounded for GEMM2) ----
    const int pm0 = pmask[b * SEQ + gr0];
    const int pm1 = pmask[b * SEQ + gr1];
    const float inv0 = (l0 > 0.f && pm0 == 1) ? 1.f / l0 : 0.f;
    const float inv1 = (l1 > 0.f && pm1 == 1) ? 1.f / l1 : 0.f;
    float* c0p = ctx + (size_t)(b * SEQ + gr0) * EMB + h * DHEAD;
    float* c1p = ctx + (size_t)(b * SEQ + gr1) * EMB + h * DHEAD;
    #pragma unroll
    for (int ni = 0; ni < 8; ni++) {
        const int col = ni * 8 + 2 * cq;
        float2 v0; v0.x = tf32r(o[ni][0] * inv0); v0.y = tf32r(o[ni][1] * inv0);
        float2 v1; v1.x = tf32r(o[ni][2] * inv1); v1.y = tf32r(o[ni][3] * inv1);
        *(float2*)(c0p + col) = v0;
        *(float2*)(c1p + col) = v1;
    }
}

// ---------------------------------------------------------------------------
// Launch
// ---------------------------------------------------------------------------
extern "C" void kernel_launch(void* const* d_in, const int* in_sizes, int n_in,
                              void* d_out, int out_size)
{
    const float* x     = (const float*)d_in[0];
    const int*   pmask = (const int*)  d_in[1];
    const float* Wqkv  = (const float*)d_in[2];
    const float* bqkv  = (const float*)d_in[3];
    const float* Wo    = (const float*)d_in[4];
    const float* bo    = (const float*)d_in[5];
    float* out = (float*)d_out;

    float *qkv, *ctx, *xr, *wqkvr, *wor;
    cudaGetSymbolAddress((void**)&qkv,   g_qkv);
    cudaGetSymbolAddress((void**)&ctx,   g_ctx);
    cudaGetSymbolAddress((void**)&xr,    g_xr);
    cudaGetSymbolAddress((void**)&wqkvr, g_wqkvr);
    cudaGetSymbolAddress((void**)&wor,   g_wor);

    cudaFuncSetAttribute(mma_gemm_kernel,
                         cudaFuncAttributeMaxDynamicSharedMemorySize,
                         GEMM_SMEM_BYTES);
    cudaFuncSetAttribute(attn_mma_kernel,
                         cudaFuncAttributeMaxDynamicSharedMemorySize,
                         ATT_SMEM_BYTES);

    // 0) tf32 pre-round (hoists cvts out of all mainloops)
    {
        const int nx = M1 * KDIM / 4, nq = KDIM * N1 / 4, no = KDIM * EMB / 4;
        round_tf32_kernel<<<(nx + 255) / 256, 256>>>(x,    xr,    nx);
        round_tf32_kernel<<<(nq + 255) / 256, 256>>>(Wqkv, wqkvr, nq);
        round_tf32_kernel<<<(no + 255) / 256, 256>>>(Wo,   wor,   no);
    }

    // 1) QKV projection (tf32 mma.sync), output tf32-rounded
    {
        dim3 grid(N1 / BN, M1 / BM);
        mma_gemm_kernel<<<grid, 128, GEMM_SMEM_BYTES>>>(xr, wqkvr, bqkv, qkv,
                                                        M1, N1, KDIM, 1);
    }

    // 2) Banded attention (tensor-core flash), ctx tf32-rounded
    {
        dim3 grid(SEQ / 64, BATCH * HEADS);
        attn_mma_kernel<<<grid, 128, ATT_SMEM_BYTES>>>(qkv, pmask, ctx);
    }

    // 3) Output projection (tf32 mma.sync), fp32 output
    {
        dim3 grid(EMB / BN, M1 / BM);
        mma_gemm_kernel<<<grid, 128, GEMM_SMEM_BYTES>>>(ctx, wor, bo, out,
                                                        M1, EMB, KDIM, 0);
    }
}

// round 12
// speedup vs baseline: 1.7756x; 1.0197x over previous
#include <cuda_runtime.h>
#include <cstdint>
#include <math.h>

// Problem constants (fixed by the reference)
#define BATCH   2
#define SEQ     2048
#define EMB     512
#define HEADS   8
#define DHEAD   64
#define WINHALF 128         // WIN/2

#define M1 (BATCH*SEQ)      // 4096 rows
#define N1 (3*EMB)          // 1536 (qkv)
#define KDIM EMB            // 512

// Scratch: __device__ globals (no allocation allowed anywhere)
__device__ float g_qkv[(size_t)M1 * N1];      // tf32-rounded qkv   ~25 MB
__device__ float g_ctx[(size_t)M1 * EMB];     // tf32-rounded ctx    ~8 MB
__device__ float g_xr[(size_t)M1 * KDIM];     // tf32-rounded x      ~8 MB
__device__ float g_wqkvr[(size_t)KDIM * N1];  // tf32-rounded Wqkv   ~3 MB
__device__ float g_wor[(size_t)KDIM * EMB];   // tf32-rounded Wo     ~1 MB

// ===========================================================================
// Helpers: mma.sync tf32 (SM80-compatible path, valid on compute_100)
// ===========================================================================
__device__ __forceinline__ uint32_t f2tf32(float x) {
    uint32_t r;
    asm("cvt.rna.tf32.f32 %0, %1;" : "=r"(r) : "f"(x));
    return r;
}
__device__ __forceinline__ float tf32r(float x) {   // round-to-tf32, as float
    return __uint_as_float(f2tf32(x));
}

__device__ __forceinline__ void mma_tf32_16x8x8(
    float* c, uint32_t a0, uint32_t a1, uint32_t a2, uint32_t a3,
    uint32_t b0, uint32_t b1)
{
    asm volatile(
        "mma.sync.aligned.m16n8k8.row.col.f32.tf32.tf32.f32 "
        "{%0,%1,%2,%3}, {%4,%5,%6,%7}, {%8,%9}, {%0,%1,%2,%3};"
        : "+f"(c[0]), "+f"(c[1]), "+f"(c[2]), "+f"(c[3])
        : "r"(a0), "r"(a1), "r"(a2), "r"(a3), "r"(b0), "r"(b1));
}

__device__ __forceinline__ uint32_t smem_u32(const void* p) {
    return (uint32_t)__cvta_generic_to_shared(p);
}

#define CP_ASYNC16(dst_u32, src_ptr) \
    asm volatile("cp.async.cg.shared.global [%0], [%1], 16;" \
                 :: "r"(dst_u32), "l"(src_ptr))
#define CP_COMMIT() asm volatile("cp.async.commit_group;" ::: "memory")
#define CP_WAIT(n)  asm volatile("cp.async.wait_group %0;" :: "n"(n) : "memory")

// ===========================================================================
// Fused tf32 rounding pre-pass: one launch for x, Wqkv, Wo (range dispatch)
// ===========================================================================
#define NX4 (M1 * KDIM / 4)
#define NQ4 (KDIM * N1 / 4)
#define NO4 (KDIM * EMB / 4)

__global__ void round3_tf32_kernel(const float* __restrict__ x,
                                   const float* __restrict__ wq,
                                   const float* __restrict__ wo,
                                   float* __restrict__ xr,
                                   float* __restrict__ wqr,
                                   float* __restrict__ wor)
{
    int i = blockIdx.x * blockDim.x + threadIdx.x;
    const float4* src;
    float4* dst;
    if (i < NX4)                 { src = (const float4*)x  + i;
                                   dst = (float4*)xr  + i; }
    else if (i < NX4 + NQ4)      { src = (const float4*)wq + (i - NX4);
                                   dst = (float4*)wqr + (i - NX4); }
    else if (i < NX4 + NQ4 + NO4){ src = (const float4*)wo + (i - NX4 - NQ4);
                                   dst = (float4*)wor + (i - NX4 - NQ4); }
    else return;
    float4 v = *src;
    v.x = tf32r(v.x); v.y = tf32r(v.y);
    v.z = tf32r(v.z); v.w = tf32r(v.w);
    *dst = v;
}

// ===========================================================================
// tf32 tensor-core GEMM: C[M,N] = A[M,K] @ B[K,N] + bias[N]
// Inputs pre-rounded to tf32 -> no cvt in the mainloop.
// 128x128 CTA tile, BK=32, 2-stage cp.async, 8 warps (2x4), warp tile 64x32,
// m16n8k8 tf32 mma. 256 threads. smem 71,680 B -> 2 CTAs/SM.
// round_out=1: store tf32-rounded (intermediates consumed by later tf32 math)
// ===========================================================================
#define BM 128
#define BN 128
#define BK 32
#define APAD 36    // As row stride (floats)
#define BPAD 136   // Bs row stride (floats)

#define GEMM_SMEM_BYTES ((2 * BM * APAD + 2 * BK * BPAD) * (int)sizeof(float))

__global__ __launch_bounds__(256, 2) void mma_gemm_kernel(
    const float* __restrict__ A, const float* __restrict__ B,
    const float* __restrict__ bias, float* __restrict__ C,
    int M, int N, int K, int round_out)
{
    extern __shared__ float smem[];
    float* AsBase = smem;                    // 2 stages of BM*APAD
    float* BsBase = smem + 2 * BM * APAD;    // 2 stages of BK*BPAD

    const int tid  = threadIdx.x;
    const int lane = tid & 31;
    const int wid  = tid >> 5;
    const int wm   = wid & 1;            // warp row (2)
    const int wn   = wid >> 1;           // warp col (4)
    const int m0   = blockIdx.y * BM;
    const int n0   = blockIdx.x * BN;

    const int aRow = wm * 64 + (lane >> 2);
    const int aCol = lane & 3;
    const int bCol = wn * 32 + (lane >> 2);
    const int bRow = lane & 3;

    float acc[4][4][4];
    #pragma unroll
    for (int mi = 0; mi < 4; mi++)
        #pragma unroll
        for (int ni = 0; ni < 4; ni++)
            #pragma unroll
            for (int r = 0; r < 4; r++) acc[mi][ni][r] = 0.f;

    const int nch = K / BK;   // 16

    auto load_tiles = [&](int s, int ch) {
        const int k0 = ch * BK;
        float* As_ = AsBase + s * BM * APAD;
        float* Bs_ = BsBase + s * BK * BPAD;
        // A: 128 rows x 32 floats -> 1024 float4, 4 per thread
        #pragma unroll
        for (int i = 0; i < 4; i++) {
            const int idx = tid + i * 256;
            const int row = idx >> 3;
            const int c4  = (idx & 7) << 2;
            const float* src = A + (size_t)(m0 + row) * K + k0 + c4;
            CP_ASYNC16(smem_u32(&As_[row * APAD + c4]), src);
        }
        // B: 32 rows x 128 floats -> 1024 float4, 4 per thread
        #pragma unroll
        for (int i = 0; i < 4; i++) {
            const int idx = tid + i * 256;
            const int row = idx >> 5;
            const int c4  = (idx & 31) << 2;
            const float* src = B + (size_t)(k0 + row) * N + n0 + c4;
            CP_ASYNC16(smem_u32(&Bs_[row * BPAD + c4]), src);
        }
        CP_COMMIT();
    };

    load_tiles(0, 0);

    for (int ch = 0; ch < nch; ch++) {
        const int s = ch & 1;
        if (ch + 1 < nch) {
            load_tiles(s ^ 1, ch + 1);
            CP_WAIT(1);
        } else {
            CP_WAIT(0);
        }
        __syncthreads();

        const float* As_ = AsBase + s * BM * APAD;
        const float* Bs_ = BsBase + s * BK * BPAD;

        #pragma unroll
        for (int ks = 0; ks < 4; ks++) {
            const int k0 = ks * 8;
            uint32_t bf[4][2];
            #pragma unroll
            for (int ni = 0; ni < 4; ni++) {
                bf[ni][0] = __float_as_uint(Bs_[(k0 + bRow)     * BPAD + bCol + ni * 8]);
                bf[ni][1] = __float_as_uint(Bs_[(k0 + bRow + 4) * BPAD + bCol + ni * 8]);
            }
            #pragma unroll
            for (int mi = 0; mi < 4; mi++) {
                const int r0 = (aRow + mi * 16) * APAD;
                const int r8 = (aRow + mi * 16 + 8) * APAD;
                uint32_t a0 = __float_as_uint(As_[r0 + k0 + aCol]);
                uint32_t a1 = __float_as_uint(As_[r8 + k0 + aCol]);
                uint32_t a2 = __float_as_uint(As_[r0 + k0 + aCol + 4]);
                uint32_t a3 = __float_as_uint(As_[r8 + k0 + aCol + 4]);
                #pragma unroll
                for (int ni = 0; ni < 4; ni++)
                    mma_tf32_16x8x8(acc[mi][ni], a0, a1, a2, a3,
                                    bf[ni][0], bf[ni][1]);
            }
        }
        __syncthreads();
    }

    // Epilogue
    const int crow = m0 + wm * 64 + (lane >> 2);
    const int ccol = n0 + wn * 32 + ((lane & 3) << 1);
    #pragma unroll
    for (int mi = 0; mi < 4; mi++) {
        #pragma unroll
        for (int ni = 0; ni < 4; ni++) {
            const int col = ccol + ni * 8;
            const float bx = bias[col], by = bias[col + 1];
            float2 v0, v1;
            v0.x = acc[mi][ni][0] + bx;  v0.y = acc[mi][ni][1] + by;
            v1.x = acc[mi][ni][2] + bx;  v1.y = acc[mi][ni][3] + by;
            if (round_out) {
                v0.x = tf32r(v0.x); v0.y = tf32r(v0.y);
                v1.x = tf32r(v1.x); v1.y = tf32r(v1.y);
            }
            *(float2*)(C + (size_t)(crow + mi * 16)     * N + col) = v0;
            *(float2*)(C + (size_t)(crow + mi * 16 + 8) * N + col) = v1;
        }
    }
}

// ===========================================================================
// Fused banded attention on tensor cores (flash-style, tf32 mma).
// qkv is pre-rounded tf32 (GEMM1 epilogue) -> staging needs no cvt.
// ctx written tf32-rounded for GEMM2.
// ===========================================================================
#define QPAD 68
#define VPAD 72
#define ATT_SMEM_BYTES ((3 * 64 * QPAD + 64 * VPAD) * (int)sizeof(float) + 64 * (int)sizeof(int))

__global__ __launch_bounds__(128) void attn_mma_kernel(
    const float* __restrict__ qkv, const int* __restrict__ pmask,
    float* __restrict__ ctx)
{
    extern __shared__ float sm[];
    float* Qs = sm;                       // [64][68]
    float* Ks = sm + 64 * QPAD;           // [64][68]
    float* Ps = sm + 2 * 64 * QPAD;       // [64][68]
    float* Vs = sm + 3 * 64 * QPAD;       // [64][72]
    int*   pms = (int*)(sm + 3 * 64 * QPAD + 64 * VPAD);  // [64]

    const int tid  = threadIdx.x;
    const int lane = tid & 31;
    const int wid  = tid >> 5;
    const int rq   = lane >> 2;    // 0..7
    const int cq   = lane & 3;     // 0..3
    const int wr0  = wid * 16;

    const int r0 = blockIdx.x * 64;
    const int b  = blockIdx.y >> 3;
    const int h  = blockIdx.y & 7;

    const float* base = qkv + (size_t)b * SEQ * N1 + h * (3 * DHEAD);

    // Load Q tile (scale 1/8 is exact on tf32 values -> no re-round)
    #pragma unroll
    for (int i = 0; i < 8; i++) {
        const int idx = tid + i * 128;
        const int row = idx >> 4;
        const int c4  = (idx & 15) << 2;
        float4 v = *(const float4*)(base + (size_t)(r0 + row) * N1 + c4);
        float* q = Qs + row * QPAD + c4;
        q[0] = v.x * 0.125f; q[1] = v.y * 0.125f;
        q[2] = v.z * 0.125f; q[3] = v.w * 0.125f;
    }

    float o[8][4];
    #pragma unroll
    for (int ni = 0; ni < 8; ni++)
        #pragma unroll
        for (int r = 0; r < 4; r++) o[ni][r] = 0.f;
    float m_old0 = -1e30f, m_old1 = -1e30f;
    float l0 = 0.f, l1 = 0.f;

    const int gr0 = r0 + wr0 + rq;
    const int gr1 = gr0 + 8;

    for (int kt = 0; kt < 5; kt++) {
        const int c0 = r0 - WINHALF + kt * 64;
        if (c0 + 63 < 0 || c0 >= SEQ) continue;   // uniform across block

        __syncthreads();   // Q ready (first pass) / prev tile fully consumed

        // Load K,V tile (zero-fill out-of-range); pmask tile
        #pragma unroll
        for (int i = 0; i < 8; i++) {
            const int idx = tid + i * 128;
            const int row = idx >> 4;
            const int c4  = (idx & 15) << 2;
            const int gc  = c0 + row;
            float4 kv = make_float4(0.f, 0.f, 0.f, 0.f);
            float4 vv = make_float4(0.f, 0.f, 0.f, 0.f);
            if (gc >= 0 && gc < SEQ) {
                kv = *(const float4*)(base + (size_t)gc * N1 + DHEAD + c4);
                vv = *(const float4*)(base + (size_t)gc * N1 + 2 * DHEAD + c4);
            }
            float* kp = Ks + row * QPAD + c4;
            kp[0] = kv.x; kp[1] = kv.y; kp[2] = kv.z; kp[3] = kv.w;
            float* vp = Vs + row * VPAD + c4;
            vp[0] = vv.x; vp[1] = vv.y; vp[2] = vv.z; vp[3] = vv.w;
        }
        if (tid < 64) {
            const int gc = c0 + tid;
            pms[tid] = (gc >= 0 && gc < SEQ) ? pmask[b * SEQ + gc] : 0;
        }
        __syncthreads();

        // ---- S = Q @ K^T ----
        float s[8][4];
        #pragma unroll
        for (int ni = 0; ni < 8; ni++)
            #pragma unroll
            for (int r = 0; r < 4; r++) s[ni][r] = 0.f;

        #pragma unroll
        for (int ks = 0; ks < 8; ks++) {
            const int k0 = ks * 8;
            uint32_t a0 = __float_as_uint(Qs[(wr0 + rq)     * QPAD + k0 + cq]);
            uint32_t a1 = __float_as_uint(Qs[(wr0 + rq + 8) * QPAD + k0 + cq]);
            uint32_t a2 = __float_as_uint(Qs[(wr0 + rq)     * QPAD + k0 + cq + 4]);
            uint32_t a3 = __float_as_uint(Qs[(wr0 + rq + 8) * QPAD + k0 + cq + 4]);
            #pragma unroll
            for (int ni = 0; ni < 8; ni++) {
                uint32_t b0 = __float_as_uint(Ks[(ni * 8 + rq) * QPAD + k0 + cq]);
                uint32_t b1 = __float_as_uint(Ks[(ni * 8 + rq) * QPAD + k0 + cq + 4]);
                mma_tf32_16x8x8(s[ni], a0, a1, a2, a3, b0, b1);
            }
        }

        // ---- band + padding mask ----
        #pragma unroll
        for (int ni = 0; ni < 8; ni++) {
            #pragma unroll
            for (int d = 0; d < 2; d++) {
                const int lc = ni * 8 + 2 * cq + d;
                const int gc = c0 + lc;
                const bool cvalid = (pms[lc] == 1);
                const int d0 = gc - gr0, d1 = gc - gr1;
                if (!cvalid || d0 > WINHALF || d0 < -WINHALF) s[ni][d]     = -1e30f;
                if (!cvalid || d1 > WINHALF || d1 < -WINHALF) s[ni][d + 2] = -1e30f;
            }
        }

        // ---- online softmax (quad-local) ----
        float tm0 = -1e30f, tm1 = -1e30f;
        #pragma unroll
        for (int ni = 0; ni < 8; ni++) {
            tm0 = fmaxf(tm0, fmaxf(s[ni][0], s[ni][1]));
            tm1 = fmaxf(tm1, fmaxf(s[ni][2], s[ni][3]));
        }
        tm0 = fmaxf(tm0, __shfl_xor_sync(0xffffffffu, tm0, 1));
        tm0 = fmaxf(tm0, __shfl_xor_sync(0xffffffffu, tm0, 2));
        tm1 = fmaxf(tm1, __shfl_xor_sync(0xffffffffu, tm1, 1));
        tm1 = fmaxf(tm1, __shfl_xor_sync(0xffffffffu, tm1, 2));

        const float mn0 = fmaxf(m_old0, tm0);
        const float mn1 = fmaxf(m_old1, tm1);
        const float sc0 = __expf(m_old0 - mn0);
        const float sc1 = __expf(m_old1 - mn1);
        m_old0 = mn0; m_old1 = mn1;

        float ts0 = 0.f, ts1 = 0.f;
        float p[8][4];
        #pragma unroll
        for (int ni = 0; ni < 8; ni++) {
            p[ni][0] = (s[ni][0] > -1e29f) ? __expf(s[ni][0] - mn0) : 0.f;
            p[ni][1] = (s[ni][1] > -1e29f) ? __expf(s[ni][1] - mn0) : 0.f;
            p[ni][2] = (s[ni][2] > -1e29f) ? __expf(s[ni][2] - mn1) : 0.f;
            p[ni][3] = (s[ni][3] > -1e29f) ? __expf(s[ni][3] - mn1) : 0.f;
            ts0 += p[ni][0] + p[ni][1];
            ts1 += p[ni][2] + p[ni][3];
        }
        ts0 += __shfl_xor_sync(0xffffffffu, ts0, 1);
        ts0 += __shfl_xor_sync(0xffffffffu, ts0, 2);
        ts1 += __shfl_xor_sync(0xffffffffu, ts1, 1);
        ts1 += __shfl_xor_sync(0xffffffffu, ts1, 2);
        l0 = l0 * sc0 + ts0;
        l1 = l1 * sc1 + ts1;

        #pragma unroll
        for (int ni = 0; ni < 8; ni++) {
            o[ni][0] *= sc0; o[ni][1] *= sc0;
            o[ni][2] *= sc1; o[ni][3] *= sc1;
        }

        // ---- P to warp-private smem rows (tf32-rounded) ----
        #pragma unroll
        for (int ni = 0; ni < 8; ni++) {
            const int col = ni * 8 + 2 * cq;
            Ps[(wr0 + rq)     * QPAD + col]     = tf32r(p[ni][0]);
            Ps[(wr0 + rq)     * QPAD + col + 1] = tf32r(p[ni][1]);
            Ps[(wr0 + rq + 8) * QPAD + col]     = tf32r(p[ni][2]);
            Ps[(wr0 + rq + 8) * QPAD + col + 1] = tf32r(p[ni][3]);
        }
        __syncwarp();

        // ---- O += P @ V ----
        #pragma unroll
        for (int ks = 0; ks < 8; ks++) {
            const int k0 = ks * 8;
            uint32_t a0 = __float_as_uint(Ps[(wr0 + rq)     * QPAD + k0 + cq]);
            uint32_t a1 = __float_as_uint(Ps[(wr0 + rq + 8) * QPAD + k0 + cq]);
            uint32_t a2 = __float_as_uint(Ps[(wr0 + rq)     * QPAD + k0 + cq + 4]);
            uint32_t a3 = __float_as_uint(Ps[(wr0 + rq + 8) * QPAD + k0 + cq + 4]);
            #pragma unroll
            for (int ni = 0; ni < 8; ni++) {
                uint32_t b0 = __float_as_uint(Vs[(k0 + cq)     * VPAD + ni * 8 + rq]);
                uint32_t b1 = __float_as_uint(Vs[(k0 + cq + 4) * VPAD + ni * 8 + rq]);
                mma_tf32_16x8x8(o[ni], a0, a1, a2, a3, b0, b1);
            }
        }
        __syncwarp();
    }

    // ---- normalize + write ctx [B,S,E] (tf32-rounded for GEMM2) ----
    const int pm0 = pmask[b * SEQ + gr0];
    const int pm1 = pmask[b * SEQ + gr1];
    const float inv0 = (l0 > 0.f && pm0 == 1) ? 1.f / l0 : 0.f;
    const float inv1 = (l1 > 0.f && pm1 == 1) ? 1.f / l1 : 0.f;
    float* c0p = ctx + (size_t)(b * SEQ + gr0) * EMB + h * DHEAD;
    float* c1p = ctx + (size_t)(b * SEQ + gr1) * EMB + h * DHEAD;
    #pragma unroll
    for (int ni = 0; ni < 8; ni++) {
        const int col = ni * 8 + 2 * cq;
        float2 v0; v0.x = tf32r(o[ni][0] * inv0); v0.y = tf32r(o[ni][1] * inv0);
        float2 v1; v1.x = tf32r(o[ni][2] * inv1); v1.y = tf32r(o[ni][3] * inv1);
        *(float2*)(c0p + col) = v0;
        *(float2*)(c1p + col) = v1;
    }
}

// ---------------------------------------------------------------------------
// Launch
// ---------------------------------------------------------------------------
extern "C" void kernel_launch(void* const* d_in, const int* in_sizes, int n_in,
                              void* d_out, int out_size)
{
    const float* x     = (const float*)d_in[0];
    const int*   pmask = (const int*)  d_in[1];
    const float* Wqkv  = (const float*)d_in[2];
    const float* bqkv  = (const float*)d_in[3];
    const float* Wo    = (const float*)d_in[4];
    const float* bo    = (const float*)d_in[5];
    float* out = (float*)d_out;

    float *qkv, *ctx, *xr, *wqkvr, *wor;
    cudaGetSymbolAddress((void**)&qkv,   g_qkv);
    cudaGetSymbolAddress((void**)&ctx,   g_ctx);
    cudaGetSymbolAddress((void**)&xr,    g_xr);
    cudaGetSymbolAddress((void**)&wqkvr, g_wqkvr);
    cudaGetSymbolAddress((void**)&wor,   g_wor);

    cudaFuncSetAttribute(mma_gemm_kernel,
                         cudaFuncAttributeMaxDynamicSharedMemorySize,
                         GEMM_SMEM_BYTES);
    cudaFuncSetAttribute(attn_mma_kernel,
                         cudaFuncAttributeMaxDynamicSharedMemorySize,
                         ATT_SMEM_BYTES);

    // 0) tf32 pre-round, single launch (x, Wqkv, Wo)
    {
        const int total = NX4 + NQ4 + NO4;
        round3_tf32_kernel<<<(total + 255) / 256, 256>>>(x, Wqkv, Wo,
                                                         xr, wqkvr, wor);
    }

    // 1) QKV projection (tf32 mma.sync), output tf32-rounded
    {
        dim3 grid(N1 / BN, M1 / BM);
        mma_gemm_kernel<<<grid, 256, GEMM_SMEM_BYTES>>>(xr, wqkvr, bqkv, qkv,
                                                        M1, N1, KDIM, 1);
    }

    // 2) Banded attention (tensor-core flash), ctx tf32-rounded
    {
        dim3 grid(SEQ / 64, BATCH * HEADS);
        attn_mma_kernel<<<grid, 128, ATT_SMEM_BYTES>>>(qkv, pmask, ctx);
    }

    // 3) Output projection (tf32 mma.sync), fp32 output
    {
        dim3 grid(EMB / BN, M1 / BM);
        mma_gemm_kernel<<<grid, 256, GEMM_SMEM_BYTES>>>(ctx, wor, bo, out,
                                                        M1, EMB, KDIM, 0);
    }
}